// round 4
// baseline (speedup 1.0000x reference)
#include <cuda_runtime.h>
#include <cstdint>
#include <cstddef>

#define DEV __device__ __forceinline__

static constexpr int SEQ   = 98;
static constexpr int NHEAD = 8;
static constexpr float QK_SCALE = 0.17677669529663688f;  // 32^-0.5

// ---------------------------------------------------------------------------
// Scratch (static device globals — allocation-free per harness rules)
// g_QKV: [3][B_*H][98][32]  (q pre-scaled)
// g_O:   [B_*98][256] attention output (c = h*32+d contiguous)
// ---------------------------------------------------------------------------
__device__ alignas(16) float g_QKV[(size_t)3 * 2048 * 8 * 98 * 32];
__device__ alignas(16) float g_O[(size_t)2048 * 98 * 256];

static constexpr size_t SZ1 = (size_t)2048 * 8 * 98 * 32;

DEV unsigned f2tf(float x) {
    unsigned u;
    asm("cvt.rna.tf32.f32 %0, %1;" : "=r"(u) : "f"(x));
    return u;
}

DEV void mma8(float c[4], unsigned a0, unsigned a1, unsigned a2, unsigned a3,
              unsigned b0, unsigned b1) {
    asm volatile(
        "mma.sync.aligned.m16n8k8.row.col.f32.tf32.tf32.f32 "
        "{%0,%1,%2,%3}, {%4,%5,%6,%7}, {%8,%9}, {%0,%1,%2,%3};\n"
        : "+f"(c[0]), "+f"(c[1]), "+f"(c[2]), "+f"(c[3])
        : "r"(a0), "r"(a1), "r"(a2), "r"(a3), "r"(b0), "r"(b1));
}

// ---------------------------------------------------------------------------
// Generic K=256 TF32 GEMM, tile 128x128x32, 256 threads (2x4 warps, 64x32 each)
// EPI 0: C = A(x) @ B(qkv_w), scatter into g_QKV (q scaled)
// EPI 1: C = g_O @ B(proj_w) + bias -> Cout (d_out)
// ---------------------------------------------------------------------------
template <int NDIM, int EPI>
__global__ __launch_bounds__(256) void gemm_k256(const float* __restrict__ A,
                                                 const float* __restrict__ B,
                                                 const float* __restrict__ bias,
                                                 float* __restrict__ Cout) {
    __shared__ float As[128][36];
    __shared__ float Bs[32][132];

    const int tid  = threadIdx.x;
    const int lane = tid & 31;
    const int warp = tid >> 5;
    const int wm = warp >> 2;       // 0..1
    const int wn = warp & 3;        // 0..3
    const int m0 = blockIdx.x * 128;
    const int n0 = blockIdx.y * 128;

    const float* Ap = (EPI == 1) ? (const float*)g_O : A;

    float acc[4][4][4];
#pragma unroll
    for (int i = 0; i < 4; i++)
#pragma unroll
        for (int j = 0; j < 4; j++)
#pragma unroll
            for (int e = 0; e < 4; e++) acc[i][j][e] = 0.f;

    for (int k0 = 0; k0 < 256; k0 += 32) {
        // register prefetch: LDGs issue here, overlap previous tile's MMAs
        float4 ar[4], br[4];
#pragma unroll
        for (int i = 0; i < 4; i++) {
            int idx = tid + i * 256;             // 1024 float4 = 128x32
            int r = idx >> 3, c4 = idx & 7;
            ar[i] = *(const float4*)(Ap + (size_t)(m0 + r) * 256 + k0 + c4 * 4);
        }
#pragma unroll
        for (int i = 0; i < 4; i++) {
            int idx = tid + i * 256;             // 1024 float4 = 32x128
            int r = idx >> 5, c4 = idx & 31;
            br[i] = *(const float4*)(B + (size_t)(k0 + r) * NDIM + n0 + c4 * 4);
        }
        __syncthreads();  // previous tile's compute done
#pragma unroll
        for (int i = 0; i < 4; i++) {
            int idx = tid + i * 256;
            int r = idx >> 3, c4 = idx & 7;
            As[r][c4 * 4 + 0] = __uint_as_float(f2tf(ar[i].x));
            As[r][c4 * 4 + 1] = __uint_as_float(f2tf(ar[i].y));
            As[r][c4 * 4 + 2] = __uint_as_float(f2tf(ar[i].z));
            As[r][c4 * 4 + 3] = __uint_as_float(f2tf(ar[i].w));
        }
#pragma unroll
        for (int i = 0; i < 4; i++) {
            int idx = tid + i * 256;
            int r = idx >> 5, c4 = idx & 31;
            Bs[r][c4 * 4 + 0] = __uint_as_float(f2tf(br[i].x));
            Bs[r][c4 * 4 + 1] = __uint_as_float(f2tf(br[i].y));
            Bs[r][c4 * 4 + 2] = __uint_as_float(f2tf(br[i].z));
            Bs[r][c4 * 4 + 3] = __uint_as_float(f2tf(br[i].w));
        }
        __syncthreads();

#pragma unroll
        for (int ks = 0; ks < 4; ks++) {
            const int kk = ks * 8 + (lane & 3);
            unsigned af[4][4];
#pragma unroll
            for (int mt = 0; mt < 4; mt++) {
                int rb = wm * 64 + mt * 16 + (lane >> 2);
                af[mt][0] = __float_as_uint(As[rb][kk]);
                af[mt][1] = __float_as_uint(As[rb + 8][kk]);
                af[mt][2] = __float_as_uint(As[rb][kk + 4]);
                af[mt][3] = __float_as_uint(As[rb + 8][kk + 4]);
            }
            unsigned bf[4][2];
#pragma unroll
            for (int nt = 0; nt < 4; nt++) {
                int cb = wn * 32 + nt * 8 + (lane >> 2);
                bf[nt][0] = __float_as_uint(Bs[kk][cb]);
                bf[nt][1] = __float_as_uint(Bs[kk + 4][cb]);
            }
#pragma unroll
            for (int mt = 0; mt < 4; mt++)
#pragma unroll
                for (int nt = 0; nt < 4; nt++)
                    mma8(acc[mt][nt], af[mt][0], af[mt][1], af[mt][2], af[mt][3],
                         bf[nt][0], bf[nt][1]);
        }
    }

    // ---- epilogue (float2 stores: c even->odd contiguous in both layouts) ----
#pragma unroll
    for (int mt = 0; mt < 4; mt++)
#pragma unroll
        for (int nt = 0; nt < 4; nt++)
#pragma unroll
            for (int half = 0; half < 2; half++) {
                int m = m0 + wm * 64 + mt * 16 + (lane >> 2) + half * 8;
                int c = n0 + wn * 32 + nt * 8 + ((lane & 3) << 1);
                float v0 = acc[mt][nt][half * 2 + 0];
                float v1 = acc[mt][nt][half * 2 + 1];
                if (EPI == 0) {
                    int bb = m / SEQ;
                    int n  = m - bb * SEQ;
                    int which = c >> 8;          // 0=q,1=k,2=v
                    int hh    = (c >> 5) & 7;
                    int d     = c & 31;          // even, d+1 same head (8|32 stride safe)
                    if (which == 0) { v0 *= QK_SCALE; v1 *= QK_SCALE; }
                    float* p = &g_QKV[(size_t)which * SZ1 +
                                      ((size_t)((bb * 8 + hh) * SEQ + n)) * 32 + d];
                    *(float2*)p = make_float2(v0, v1);
                } else {
                    float2 bv = *(const float2*)&bias[c];
                    *(float2*)&Cout[(size_t)m * 256 + c] =
                        make_float2(v0 + bv.x, v1 + bv.y);
                }
            }
}

// ---------------------------------------------------------------------------
// Fused window attention: one CTA per (b, h). 256 threads.
// Smem: Qs[112][36] Ks[104][36] Vs[104][36] Ss[112][108] Bt[508] = 96496 B
// ---------------------------------------------------------------------------
__global__ __launch_bounds__(256) void attn_kernel(const float* __restrict__ mask,
                                                   const float* __restrict__ bias_table) {
    extern __shared__ float sm[];
    float* Qs = sm;             // 112*36 = 4032
    float* Ks = sm + 4032;      // 104*36 = 3744
    float* Vs = sm + 7776;      // 104*36 = 3744
    float* Ss = sm + 11520;     // 112*108 = 12096
    float* Bt = sm + 23616;     // 508 (507 used)

    const int tid  = threadIdx.x;
    const int lane = tid & 31;
    const int warp = tid >> 5;
    const int b = blockIdx.x >> 3;
    const int h = blockIdx.x & 7;

    const float* Qg = g_QKV + (size_t)(b * 8 + h) * SEQ * 32;
    const float* Kg = Qg + SZ1;
    const float* Vg = Qg + 2 * SZ1;

    // stage this head's bias-table slice into smem (507 entries)
    for (int i = tid; i < 507; i += 256) Bt[i] = __ldg(&bias_table[i * NHEAD + h]);

    // load Q/K/V (98x32 floats each = 784 float4), tf32-round at store
#pragma unroll
    for (int i = 0; i < 4; i++) {
        int idx = tid + i * 256;
        if (idx < 784) {
            int r = idx >> 3, c4 = idx & 7;
            float4 q = *(const float4*)(Qg + (size_t)idx * 4);
            float4 k = *(const float4*)(Kg + (size_t)idx * 4);
            float4 v = *(const float4*)(Vg + (size_t)idx * 4);
            int o = r * 36 + c4 * 4;
            Qs[o + 0] = __uint_as_float(f2tf(q.x));
            Qs[o + 1] = __uint_as_float(f2tf(q.y));
            Qs[o + 2] = __uint_as_float(f2tf(q.z));
            Qs[o + 3] = __uint_as_float(f2tf(q.w));
            Ks[o + 0] = __uint_as_float(f2tf(k.x));
            Ks[o + 1] = __uint_as_float(f2tf(k.y));
            Ks[o + 2] = __uint_as_float(f2tf(k.z));
            Ks[o + 3] = __uint_as_float(f2tf(k.w));
            Vs[o + 0] = __uint_as_float(f2tf(v.x));
            Vs[o + 1] = __uint_as_float(f2tf(v.y));
            Vs[o + 2] = __uint_as_float(f2tf(v.z));
            Vs[o + 3] = __uint_as_float(f2tf(v.w));
        }
    }
    // zero padding rows (Q: 98..111, K/V: 98..103) — required so padded S cols are 0
    for (int i = tid; i < 14 * 36; i += 256) Qs[98 * 36 + i] = 0.f;
    for (int i = tid; i < 6 * 36; i += 256) { Ks[98 * 36 + i] = 0.f; Vs[98 * 36 + i] = 0.f; }
    __syncthreads();

    // ---- S = Q K^T : 7 (m16) x 13 (n8) tiles, K=32 ----
    for (int t = warp; t < 91; t += 8) {
        int mt = t / 13, nt = t - mt * 13;
        float c[4] = {0.f, 0.f, 0.f, 0.f};
        int ra = mt * 16 + (lane >> 2);
        int rb = nt * 8 + (lane >> 2);
#pragma unroll
        for (int ks = 0; ks < 4; ks++) {
            int kk = ks * 8 + (lane & 3);
            unsigned a0 = __float_as_uint(Qs[ra * 36 + kk]);
            unsigned a1 = __float_as_uint(Qs[(ra + 8) * 36 + kk]);
            unsigned a2 = __float_as_uint(Qs[ra * 36 + kk + 4]);
            unsigned a3 = __float_as_uint(Qs[(ra + 8) * 36 + kk + 4]);
            unsigned b0 = __float_as_uint(Ks[rb * 36 + kk]);
            unsigned b1 = __float_as_uint(Ks[rb * 36 + kk + 4]);
            mma8(c, a0, a1, a2, a3, b0, b1);
        }
        int row = mt * 16 + (lane >> 2);
        int col = nt * 8 + ((lane & 3) << 1);
        Ss[row * 108 + col]           = c[0];
        Ss[row * 108 + col + 1]       = c[1];
        Ss[(row + 8) * 108 + col]     = c[2];
        Ss[(row + 8) * 108 + col + 1] = c[3];
    }
    __syncthreads();

    // ---- bias + mask + softmax (warp per row) ----
    const float* mbase = mask + (size_t)(b & 63) * SEQ * SEQ;
    for (int r = warp; r < SEQ; r += 8) {
        int zr = r / 49, rr = r - zr * 49;
        int yr = rr / 7, xr = rr - yr * 7;
        float* srow = Ss + r * 108;
        const float* mrow = mbase + r * SEQ;
        float v[4];
        float mx = -1e30f;
#pragma unroll
        for (int j = 0; j < 4; j++) {
            int cidx = lane + j * 32;
            if (cidx < SEQ) {
                int zc = cidx / 49, rc = cidx - zc * 49;
                int yc = rc / 7, xc = rc - yc * 7;
                int idx = (zr - zc + 1) * 169 + (yr - yc + 6) * 13 + (xr - xc + 6);
                v[j] = srow[cidx] + __ldg(&mrow[cidx]) + Bt[idx];
                mx = fmaxf(mx, v[j]);
            } else {
                v[j] = -1e30f;
            }
        }
#pragma unroll
        for (int o = 16; o; o >>= 1) mx = fmaxf(mx, __shfl_xor_sync(0xffffffffu, mx, o));
        float s = 0.f;
#pragma unroll
        for (int j = 0; j < 4; j++) {
            float e = __expf(v[j] - mx);   // invalid lanes underflow to 0
            v[j] = e;
            s += e;
        }
#pragma unroll
        for (int o = 16; o; o >>= 1) s += __shfl_xor_sync(0xffffffffu, s, o);
        float inv = 1.f / s;
#pragma unroll
        for (int j = 0; j < 4; j++) {
            int cidx = lane + j * 32;
            if (cidx < SEQ) srow[cidx] = v[j] * inv;
            // cols 98..103 keep their mma value 0 (K pad rows zeroed) -> safe pad for PV
        }
    }
    __syncthreads();

    // ---- O = P V : 7 (m16) x 4 (n8) tiles, K=104 ----
    float* Ob = g_O + (size_t)b * SEQ * 256 + h * 32;
    for (int t = warp; t < 28; t += 8) {
        int mt = t >> 2, nt = t & 3;
        float c[4] = {0.f, 0.f, 0.f, 0.f};
        int ra = mt * 16 + (lane >> 2);
        int cb = nt * 8 + (lane >> 2);
#pragma unroll
        for (int ks = 0; ks < 13; ks++) {
            int kk = ks * 8 + (lane & 3);
            unsigned a0 = f2tf(Ss[ra * 108 + kk]);
            unsigned a1 = f2tf(Ss[(ra + 8) * 108 + kk]);
            unsigned a2 = f2tf(Ss[ra * 108 + kk + 4]);
            unsigned a3 = f2tf(Ss[(ra + 8) * 108 + kk + 4]);
            unsigned b0 = __float_as_uint(Vs[kk * 36 + cb]);
            unsigned b1 = __float_as_uint(Vs[(kk + 4) * 36 + cb]);
            mma8(c, a0, a1, a2, a3, b0, b1);
        }
        int row = mt * 16 + (lane >> 2);
        int col = nt * 8 + ((lane & 3) << 1);
        if (row < SEQ)
            *(float2*)&Ob[(size_t)row * 256 + col] = make_float2(c[0], c[1]);
        if (row + 8 < SEQ)
            *(float2*)&Ob[(size_t)(row + 8) * 256 + col] = make_float2(c[2], c[3]);
    }
}

// ---------------------------------------------------------------------------
extern "C" void kernel_launch(void* const* d_in, const int* in_sizes, int n_in,
                              void* d_out, int out_size) {
    const float* x          = (const float*)d_in[0];
    const float* mask       = (const float*)d_in[1];
    const float* qkv_w      = (const float*)d_in[2];
    const float* proj_w     = (const float*)d_in[3];
    const float* proj_b     = (const float*)d_in[4];
    const float* bias_table = (const float*)d_in[5];
    float* out = (float*)d_out;

    (void)in_sizes; (void)n_in; (void)out_size;

    // QKV projection: [200704,256] x [256,768] -> scatter to g_QKV
    gemm_k256<768, 0><<<dim3(1568, 6), 256>>>(x, qkv_w, nullptr, nullptr);

    // Fused attention, one CTA per (b,h)
    cudaFuncSetAttribute(attn_kernel, cudaFuncAttributeMaxDynamicSharedMemorySize, 96496);
    attn_kernel<<<2048 * 8, 256, 96496>>>(mask, bias_table);

    // Output projection: [200704,256] x [256,256] + bias -> d_out
    gemm_k256<256, 1><<<dim3(1568, 2), 256>>>(nullptr, proj_w, proj_b, out);
}

// round 9
// speedup vs baseline: 1.1234x; 1.1234x over previous
#include <cuda_runtime.h>
#include <cstdint>
#include <cstddef>

#define DEV __device__ __forceinline__

static constexpr int SEQ   = 98;
static constexpr int NHEAD = 8;
static constexpr float QK_SCALE = 0.17677669529663688f;  // 32^-0.5

// ---------------------------------------------------------------------------
// Scratch (static device globals — allocation-free per harness rules)
// ---------------------------------------------------------------------------
__device__ alignas(16) float g_QKV[(size_t)3 * 2048 * 8 * 98 * 32];
__device__ alignas(16) float g_O[(size_t)2048 * 98 * 256];

static constexpr size_t SZ1 = (size_t)2048 * 8 * 98 * 32;

DEV unsigned f2tf(float x) {
    unsigned u;
    asm("cvt.rna.tf32.f32 %0, %1;" : "=r"(u) : "f"(x));
    return u;
}

DEV float4 f2tf4(float4 v) {
    return make_float4(__uint_as_float(f2tf(v.x)), __uint_as_float(f2tf(v.y)),
                       __uint_as_float(f2tf(v.z)), __uint_as_float(f2tf(v.w)));
}

DEV void mma8(float c[4], unsigned a0, unsigned a1, unsigned a2, unsigned a3,
              unsigned b0, unsigned b1) {
    asm volatile(
        "mma.sync.aligned.m16n8k8.row.col.f32.tf32.tf32.f32 "
        "{%0,%1,%2,%3}, {%4,%5,%6,%7}, {%8,%9}, {%0,%1,%2,%3};\n"
        : "+f"(c[0]), "+f"(c[1]), "+f"(c[2]), "+f"(c[3])
        : "r"(a0), "r"(a1), "r"(a2), "r"(a3), "r"(b0), "r"(b1));
}

// ---------------------------------------------------------------------------
// Generic K=256 TF32 GEMM, tile 128x128x32, 256 threads (2x4 warps, 64x32 each)
// grid = (N/128, M/128): N-tile fastest so waves share A tiles via L2
// launch_bounds(256,2): pin <=128 regs -> guaranteed 2 CTAs/SM
// ---------------------------------------------------------------------------
template <int NDIM, int EPI>
__global__ __launch_bounds__(256, 2) void gemm_k256(const float* __restrict__ A,
                                                    const float* __restrict__ B,
                                                    const float* __restrict__ bias,
                                                    float* __restrict__ Cout) {
    __shared__ float As[128][36];
    __shared__ float Bs[32][132];

    const int tid  = threadIdx.x;
    const int lane = tid & 31;
    const int warp = tid >> 5;
    const int wm = warp >> 2;       // 0..1
    const int wn = warp & 3;        // 0..3
    const int m0 = blockIdx.y * 128;   // M-tile on slow axis (A reuse in L2)
    const int n0 = blockIdx.x * 128;   // N-tile on fast axis

    const float* Ap = (EPI == 1) ? (const float*)g_O : A;

    float acc[4][4][4];
#pragma unroll
    for (int i = 0; i < 4; i++)
#pragma unroll
        for (int j = 0; j < 4; j++)
#pragma unroll
            for (int e = 0; e < 4; e++) acc[i][j][e] = 0.f;

    for (int k0 = 0; k0 < 256; k0 += 32) {
        // register prefetch: LDGs issue here, overlap previous tile's MMAs
        float4 ar[4], br[4];
#pragma unroll
        for (int i = 0; i < 4; i++) {
            int idx = tid + i * 256;             // 1024 float4 = 128x32
            int r = idx >> 3, c4 = idx & 7;
            ar[i] = *(const float4*)(Ap + (size_t)(m0 + r) * 256 + k0 + c4 * 4);
        }
#pragma unroll
        for (int i = 0; i < 4; i++) {
            int idx = tid + i * 256;             // 1024 float4 = 32x128
            int r = idx >> 5, c4 = idx & 31;
            br[i] = *(const float4*)(B + (size_t)(k0 + r) * NDIM + n0 + c4 * 4);
        }
        __syncthreads();  // previous tile's compute done
#pragma unroll
        for (int i = 0; i < 4; i++) {
            int idx = tid + i * 256;
            int r = idx >> 3, c4 = idx & 7;
            *(float4*)&As[r][c4 * 4] = f2tf4(ar[i]);     // STS.128
        }
#pragma unroll
        for (int i = 0; i < 4; i++) {
            int idx = tid + i * 256;
            int r = idx >> 5, c4 = idx & 31;
            *(float4*)&Bs[r][c4 * 4] = f2tf4(br[i]);     // STS.128
        }
        __syncthreads();

#pragma unroll
        for (int ks = 0; ks < 4; ks++) {
            const int kk = ks * 8 + (lane & 3);
            unsigned af[4][4];
#pragma unroll
            for (int mt = 0; mt < 4; mt++) {
                int rb = wm * 64 + mt * 16 + (lane >> 2);
                af[mt][0] = __float_as_uint(As[rb][kk]);
                af[mt][1] = __float_as_uint(As[rb + 8][kk]);
                af[mt][2] = __float_as_uint(As[rb][kk + 4]);
                af[mt][3] = __float_as_uint(As[rb + 8][kk + 4]);
            }
            unsigned bf[4][2];
#pragma unroll
            for (int nt = 0; nt < 4; nt++) {
                int cb = wn * 32 + nt * 8 + (lane >> 2);
                bf[nt][0] = __float_as_uint(Bs[kk][cb]);
                bf[nt][1] = __float_as_uint(Bs[kk + 4][cb]);
            }
#pragma unroll
            for (int mt = 0; mt < 4; mt++)
#pragma unroll
                for (int nt = 0; nt < 4; nt++)
                    mma8(acc[mt][nt], af[mt][0], af[mt][1], af[mt][2], af[mt][3],
                         bf[nt][0], bf[nt][1]);
        }
    }

    // ---- epilogue (float2 stores) ----
#pragma unroll
    for (int mt = 0; mt < 4; mt++)
#pragma unroll
        for (int nt = 0; nt < 4; nt++)
#pragma unroll
            for (int half = 0; half < 2; half++) {
                int m = m0 + wm * 64 + mt * 16 + (lane >> 2) + half * 8;
                int c = n0 + wn * 32 + nt * 8 + ((lane & 3) << 1);
                float v0 = acc[mt][nt][half * 2 + 0];
                float v1 = acc[mt][nt][half * 2 + 1];
                if (EPI == 0) {
                    int bb = m / SEQ;
                    int n  = m - bb * SEQ;
                    int which = c >> 8;          // 0=q,1=k,2=v
                    int hh    = (c >> 5) & 7;
                    int d     = c & 31;
                    if (which == 0) { v0 *= QK_SCALE; v1 *= QK_SCALE; }
                    float* p = &g_QKV[(size_t)which * SZ1 +
                                      ((size_t)((bb * 8 + hh) * SEQ + n)) * 32 + d];
                    *(float2*)p = make_float2(v0, v1);
                } else {
                    float2 bv = *(const float2*)&bias[c];
                    *(float2*)&Cout[(size_t)m * 256 + c] =
                        make_float2(v0 + bv.x, v1 + bv.y);
                }
            }
}

// ---------------------------------------------------------------------------
// Fused window attention: one CTA per (b, h). 512 threads (16 warps).
// Smem: Qs[112][36] Ks[104][36] Vs[104][36] Ss[112][108] Bt[508] = 96496 B
// launch_bounds(512,2): pin <=64 regs -> guaranteed 2 CTAs/SM (1024 thr)
// ---------------------------------------------------------------------------
__global__ __launch_bounds__(512, 2) void attn_kernel(const float* __restrict__ mask,
                                                      const float* __restrict__ bias_table) {
    extern __shared__ float sm[];
    float* Qs = sm;             // 112*36 = 4032
    float* Ks = sm + 4032;      // 104*36 = 3744
    float* Vs = sm + 7776;      // 104*36 = 3744
    float* Ss = sm + 11520;     // 112*108 = 12096
    float* Bt = sm + 23616;     // 508 (507 used)

    const int tid  = threadIdx.x;
    const int lane = tid & 31;
    const int warp = tid >> 5;   // 0..15
    const int b = blockIdx.x >> 3;
    const int h = blockIdx.x & 7;

    const float* Qg = g_QKV + (size_t)(b * 8 + h) * SEQ * 32;
    const float* Kg = Qg + SZ1;
    const float* Vg = Qg + 2 * SZ1;

    // stage this head's bias-table slice into smem (507 entries)
    if (tid < 507) Bt[tid] = __ldg(&bias_table[tid * NHEAD + h]);

    // load Q/K/V (98x32 floats each = 784 float4), tf32-round at store
#pragma unroll
    for (int i = 0; i < 2; i++) {
        int idx = tid + i * 512;
        if (idx < 784) {
            int r = idx >> 3, c4 = idx & 7;
            float4 q = *(const float4*)(Qg + (size_t)idx * 4);
            float4 k = *(const float4*)(Kg + (size_t)idx * 4);
            float4 v = *(const float4*)(Vg + (size_t)idx * 4);
            int o = r * 36 + c4 * 4;
            *(float4*)&Qs[o] = f2tf4(q);
            *(float4*)&Ks[o] = f2tf4(k);
            *(float4*)&Vs[o] = f2tf4(v);
        }
    }
    // zero padding rows (Q: 98..111, K/V: 98..103)
    if (tid < 504) Qs[98 * 36 + tid] = 0.f;
    if (tid < 216) { Ks[98 * 36 + tid] = 0.f; Vs[98 * 36 + tid] = 0.f; }
    __syncthreads();

    // ---- S = Q K^T : 7 (m16) x 13 (n8) tiles, K=32 ----
    for (int t = warp; t < 91; t += 16) {
        int mt = t / 13, nt = t - mt * 13;
        float c[4] = {0.f, 0.f, 0.f, 0.f};
        int ra = mt * 16 + (lane >> 2);
        int rb = nt * 8 + (lane >> 2);
#pragma unroll
        for (int ks = 0; ks < 4; ks++) {
            int kk = ks * 8 + (lane & 3);
            unsigned a0 = __float_as_uint(Qs[ra * 36 + kk]);
            unsigned a1 = __float_as_uint(Qs[(ra + 8) * 36 + kk]);
            unsigned a2 = __float_as_uint(Qs[ra * 36 + kk + 4]);
            unsigned a3 = __float_as_uint(Qs[(ra + 8) * 36 + kk + 4]);
            unsigned b0 = __float_as_uint(Ks[rb * 36 + kk]);
            unsigned b1 = __float_as_uint(Ks[rb * 36 + kk + 4]);
            mma8(c, a0, a1, a2, a3, b0, b1);
        }
        int row = mt * 16 + (lane >> 2);
        int col = nt * 8 + ((lane & 3) << 1);
        Ss[row * 108 + col]           = c[0];
        Ss[row * 108 + col + 1]       = c[1];
        Ss[(row + 8) * 108 + col]     = c[2];
        Ss[(row + 8) * 108 + col + 1] = c[3];
    }
    __syncthreads();

    // ---- bias + mask + softmax (warp per row) ----
    // column spatial decomposition is row-invariant: hoist it
    int coff[4];
#pragma unroll
    for (int j = 0; j < 4; j++) {
        int cidx = lane + j * 32;
        if (cidx < SEQ) {
            int zc = cidx / 49, rc = cidx - zc * 49;
            int yc = rc / 7, xc = rc - yc * 7;
            coff[j] = -(zc * 169 + yc * 13 + xc);
        } else coff[j] = 0;
    }
    const float* mbase = mask + (size_t)(b & 63) * SEQ * SEQ;
    for (int r = warp; r < SEQ; r += 16) {
        int zr = r / 49, rr = r - zr * 49;
        int yr = rr / 7, xr = rr - yr * 7;
        int base = (zr + 1) * 169 + (yr + 6) * 13 + (xr + 6);
        float* srow = Ss + r * 108;
        const float* mrow = mbase + r * SEQ;
        float v[4];
        float mx = -1e30f;
#pragma unroll
        for (int j = 0; j < 4; j++) {
            int cidx = lane + j * 32;
            if (cidx < SEQ) {
                v[j] = srow[cidx] + __ldg(&mrow[cidx]) + Bt[base + coff[j]];
                mx = fmaxf(mx, v[j]);
            } else {
                v[j] = -1e30f;
            }
        }
#pragma unroll
        for (int o = 16; o; o >>= 1) mx = fmaxf(mx, __shfl_xor_sync(0xffffffffu, mx, o));
        float s = 0.f;
#pragma unroll
        for (int j = 0; j < 4; j++) {
            float e = __expf(v[j] - mx);   // invalid lanes underflow to 0
            v[j] = e;
            s += e;
        }
#pragma unroll
        for (int o = 16; o; o >>= 1) s += __shfl_xor_sync(0xffffffffu, s, o);
        float inv = 1.f / s;
#pragma unroll
        for (int j = 0; j < 4; j++) {
            int cidx = lane + j * 32;
            if (cidx < SEQ) srow[cidx] = v[j] * inv;
        }
    }
    __syncthreads();

    // ---- O = P V : 7 (m16) x 4 (n8) tiles, K=104 ----
    float* Ob = g_O + (size_t)b * SEQ * 256 + h * 32;
    for (int t = warp; t < 28; t += 16) {
        int mt = t >> 2, nt = t & 3;
        float c[4] = {0.f, 0.f, 0.f, 0.f};
        int ra = mt * 16 + (lane >> 2);
        int cb = nt * 8 + (lane >> 2);
#pragma unroll
        for (int ks = 0; ks < 13; ks++) {
            int kk = ks * 8 + (lane & 3);
            unsigned a0 = f2tf(Ss[ra * 108 + kk]);          // softmax out: must round
            unsigned a1 = f2tf(Ss[(ra + 8) * 108 + kk]);
            unsigned a2 = f2tf(Ss[ra * 108 + kk + 4]);
            unsigned a3 = f2tf(Ss[(ra + 8) * 108 + kk + 4]);
            unsigned b0 = __float_as_uint(Vs[kk * 36 + cb]); // already tf32-rounded
            unsigned b1 = __float_as_uint(Vs[(kk + 4) * 36 + cb]);
            mma8(c, a0, a1, a2, a3, b0, b1);
        }
        int row = mt * 16 + (lane >> 2);
        int col = nt * 8 + ((lane & 3) << 1);
        if (row < SEQ)
            *(float2*)&Ob[(size_t)row * 256 + col] = make_float2(c[0], c[1]);
        if (row + 8 < SEQ)
            *(float2*)&Ob[(size_t)(row + 8) * 256 + col] = make_float2(c[2], c[3]);
    }
}

// ---------------------------------------------------------------------------
extern "C" void kernel_launch(void* const* d_in, const int* in_sizes, int n_in,
                              void* d_out, int out_size) {
    const float* x          = (const float*)d_in[0];
    const float* mask       = (const float*)d_in[1];
    const float* qkv_w      = (const float*)d_in[2];
    const float* proj_w     = (const float*)d_in[3];
    const float* proj_b     = (const float*)d_in[4];
    const float* bias_table = (const float*)d_in[5];
    float* out = (float*)d_out;

    (void)in_sizes; (void)n_in; (void)out_size;

    // QKV projection: [200704,256] x [256,768] -> scatter to g_QKV
    // grid (N,M): N fastest => each wave shares A tiles in L2 (saves ~1GB DRAM)
    gemm_k256<768, 0><<<dim3(6, 1568), 256>>>(x, qkv_w, nullptr, nullptr);

    // Fused attention, one CTA per (b,h), 512 threads
    cudaFuncSetAttribute(attn_kernel, cudaFuncAttributeMaxDynamicSharedMemorySize, 96496);
    attn_kernel<<<2048 * 8, 512, 96496>>>(mask, bias_table);

    // Output projection: [200704,256] x [256,256] + bias -> d_out
    gemm_k256<256, 1><<<dim3(2, 1568), 256>>>(nullptr, proj_w, proj_b, out);
}

// round 10
// speedup vs baseline: 1.3460x; 1.1981x over previous
#include <cuda_runtime.h>
#include <cuda_fp16.h>
#include <cstdint>
#include <cstddef>

#define DEV __device__ __forceinline__

static constexpr int SEQ   = 98;
static constexpr int NHEAD = 8;
static constexpr float QK_SCALE = 0.17677669529663688f;  // 32^-0.5

// ---------------------------------------------------------------------------
// Scratch (static device globals — allocation-free per harness rules)
// ---------------------------------------------------------------------------
__device__ alignas(16) float g_QKV[(size_t)3 * 2048 * 8 * 98 * 32];
__device__ alignas(16) float g_O[(size_t)2048 * 98 * 256];

static constexpr size_t SZ1 = (size_t)2048 * 8 * 98 * 32;

DEV unsigned f2tf(float x) {
    unsigned u;
    asm("cvt.rna.tf32.f32 %0, %1;" : "=r"(u) : "f"(x));
    return u;
}

DEV float4 f2tf4(float4 v) {
    return make_float4(__uint_as_float(f2tf(v.x)), __uint_as_float(f2tf(v.y)),
                       __uint_as_float(f2tf(v.z)), __uint_as_float(f2tf(v.w)));
}

DEV void mma8(float c[4], unsigned a0, unsigned a1, unsigned a2, unsigned a3,
              unsigned b0, unsigned b1) {
    asm volatile(
        "mma.sync.aligned.m16n8k8.row.col.f32.tf32.tf32.f32 "
        "{%0,%1,%2,%3}, {%4,%5,%6,%7}, {%8,%9}, {%0,%1,%2,%3};\n"
        : "+f"(c[0]), "+f"(c[1]), "+f"(c[2]), "+f"(c[3])
        : "r"(a0), "r"(a1), "r"(a2), "r"(a3), "r"(b0), "r"(b1));
}

DEV void mma16(float c[4], unsigned a0, unsigned a1, unsigned a2, unsigned a3,
               unsigned b0, unsigned b1) {
    asm volatile(
        "mma.sync.aligned.m16n8k16.row.col.f32.f16.f16.f32 "
        "{%0,%1,%2,%3}, {%4,%5,%6,%7}, {%8,%9}, {%0,%1,%2,%3};\n"
        : "+f"(c[0]), "+f"(c[1]), "+f"(c[2]), "+f"(c[3])
        : "r"(a0), "r"(a1), "r"(a2), "r"(a3), "r"(b0), "r"(b1));
}

DEV uint32_t smem_u32(const void* p) { return (uint32_t)__cvta_generic_to_shared(p); }

DEV void ldsm_x4(unsigned& r0, unsigned& r1, unsigned& r2, unsigned& r3, uint32_t a) {
    asm volatile("ldmatrix.sync.aligned.m8n8.x4.shared.b16 {%0,%1,%2,%3}, [%4];"
                 : "=r"(r0), "=r"(r1), "=r"(r2), "=r"(r3) : "r"(a));
}

DEV void ldsm_x2t(unsigned& r0, unsigned& r1, uint32_t a) {
    asm volatile("ldmatrix.sync.aligned.m8n8.x2.trans.shared.b16 {%0,%1}, [%2];"
                 : "=r"(r0), "=r"(r1) : "r"(a));
}

DEV uint2 f4_to_h4(float4 v) {
    __half2 h0 = __floats2half2_rn(v.x, v.y);
    __half2 h1 = __floats2half2_rn(v.z, v.w);
    uint2 u;
    u.x = *reinterpret_cast<uint32_t*>(&h0);
    u.y = *reinterpret_cast<uint32_t*>(&h1);
    return u;
}

// ---------------------------------------------------------------------------
// FP16 K=256 GEMM, tile 128x128x32, 256 threads (2x4 warps, 64x32 each)
// fp32 global -> rn fp16 smem -> ldmatrix -> m16n8k16 (fp32 accum)
// As: [128][40] halves (80B row, ldmatrix conflict-free)
// Bs: [32][136] halves (272B row, x2.trans conflict-free)
// grid = (N/128, M/128): N fastest -> A tiles shared via L2
// ---------------------------------------------------------------------------
template <int NDIM, int EPI>
__global__ __launch_bounds__(256, 2) void gemm_f16(const float* __restrict__ A,
                                                   const float* __restrict__ B,
                                                   const float* __restrict__ bias,
                                                   float* __restrict__ Cout) {
    __shared__ __half As[128][40];
    __shared__ __half Bs[32][136];

    const int tid  = threadIdx.x;
    const int lane = tid & 31;
    const int warp = tid >> 5;
    const int wm = warp >> 2;       // 0..1
    const int wn = warp & 3;        // 0..3
    const int m0 = blockIdx.y * 128;
    const int n0 = blockIdx.x * 128;

    const float* Ap = (EPI == 1) ? (const float*)g_O : A;

    // ldmatrix per-lane base addresses
    // A x4: lanes 0-7 rows m..m+7 (k lo), 8-15 rows m+8.. (k lo),
    //       16-23 rows m..m+7 (k hi), 24-31 rows m+8.. (k hi)
    const int a_row = wm * 64 + (lane & 7) + ((lane >> 3) & 1) * 8;
    const uint32_t a_base = smem_u32(&As[a_row][((lane >> 4) & 1) * 8]);
    // B x2.trans: lanes 0-15 rows k..k+15 at n-col base
    const uint32_t b_base = smem_u32(&Bs[0][0]) + (uint32_t)((lane & 15) * 136 + wn * 32) * 2;

    float acc[4][4][4];
#pragma unroll
    for (int i = 0; i < 4; i++)
#pragma unroll
        for (int j = 0; j < 4; j++)
#pragma unroll
            for (int e = 0; e < 4; e++) acc[i][j][e] = 0.f;

    for (int k0 = 0; k0 < 256; k0 += 32) {
        float4 ar[4], br[4];
#pragma unroll
        for (int i = 0; i < 4; i++) {
            int idx = tid + i * 256;             // 1024 float4 = 128x32
            int r = idx >> 3, c4 = idx & 7;
            ar[i] = *(const float4*)(Ap + (size_t)(m0 + r) * 256 + k0 + c4 * 4);
        }
#pragma unroll
        for (int i = 0; i < 4; i++) {
            int idx = tid + i * 256;             // 1024 float4 = 32x128
            int r = idx >> 5, c4 = idx & 31;
            br[i] = *(const float4*)(B + (size_t)(k0 + r) * NDIM + n0 + c4 * 4);
        }
        __syncthreads();  // previous tile's compute done
#pragma unroll
        for (int i = 0; i < 4; i++) {
            int idx = tid + i * 256;
            int r = idx >> 3, c4 = idx & 7;
            *(uint2*)&As[r][c4 * 4] = f4_to_h4(ar[i]);   // STS.64
        }
#pragma unroll
        for (int i = 0; i < 4; i++) {
            int idx = tid + i * 256;
            int r = idx >> 5, c4 = idx & 31;
            *(uint2*)&Bs[r][c4 * 4] = f4_to_h4(br[i]);   // STS.64
        }
        __syncthreads();

#pragma unroll
        for (int ks = 0; ks < 2; ks++) {                 // two k16 steps
            unsigned af[4][4];
#pragma unroll
            for (int mt = 0; mt < 4; mt++)
                ldsm_x4(af[mt][0], af[mt][1], af[mt][2], af[mt][3],
                        a_base + (uint32_t)(mt * 16 * 80 + ks * 32));
            unsigned bf[4][2];
#pragma unroll
            for (int nt = 0; nt < 4; nt++)
                ldsm_x2t(bf[nt][0], bf[nt][1],
                         b_base + (uint32_t)(ks * 16 * 272 + nt * 16));
#pragma unroll
            for (int mt = 0; mt < 4; mt++)
#pragma unroll
                for (int nt = 0; nt < 4; nt++)
                    mma16(acc[mt][nt], af[mt][0], af[mt][1], af[mt][2], af[mt][3],
                          bf[nt][0], bf[nt][1]);
        }
    }

    // ---- epilogue (float2 stores; fp16 mma C layout == tf32 layout) ----
#pragma unroll
    for (int mt = 0; mt < 4; mt++)
#pragma unroll
        for (int nt = 0; nt < 4; nt++)
#pragma unroll
            for (int half = 0; half < 2; half++) {
                int m = m0 + wm * 64 + mt * 16 + (lane >> 2) + half * 8;
                int c = n0 + wn * 32 + nt * 8 + ((lane & 3) << 1);
                float v0 = acc[mt][nt][half * 2 + 0];
                float v1 = acc[mt][nt][half * 2 + 1];
                if (EPI == 0) {
                    int bb = m / SEQ;
                    int n  = m - bb * SEQ;
                    int which = c >> 8;          // 0=q,1=k,2=v
                    int hh    = (c >> 5) & 7;
                    int d     = c & 31;
                    if (which == 0) { v0 *= QK_SCALE; v1 *= QK_SCALE; }
                    float* p = &g_QKV[(size_t)which * SZ1 +
                                      ((size_t)((bb * 8 + hh) * SEQ + n)) * 32 + d];
                    *(float2*)p = make_float2(v0, v1);
                } else {
                    float2 bv = *(const float2*)&bias[c];
                    *(float2*)&Cout[(size_t)m * 256 + c] =
                        make_float2(v0 + bv.x, v1 + bv.y);
                }
            }
}

// ---------------------------------------------------------------------------
// Fused window attention (unchanged, tf32): one CTA per (b, h). 512 threads.
// Smem: Qs[112][36] Ks[104][36] Vs[104][36] Ss[112][108] Bt[508] = 96496 B
// ---------------------------------------------------------------------------
__global__ __launch_bounds__(512, 2) void attn_kernel(const float* __restrict__ mask,
                                                      const float* __restrict__ bias_table) {
    extern __shared__ float sm[];
    float* Qs = sm;             // 112*36 = 4032
    float* Ks = sm + 4032;      // 104*36 = 3744
    float* Vs = sm + 7776;      // 104*36 = 3744
    float* Ss = sm + 11520;     // 112*108 = 12096
    float* Bt = sm + 23616;     // 508 (507 used)

    const int tid  = threadIdx.x;
    const int lane = tid & 31;
    const int warp = tid >> 5;   // 0..15
    const int b = blockIdx.x >> 3;
    const int h = blockIdx.x & 7;

    const float* Qg = g_QKV + (size_t)(b * 8 + h) * SEQ * 32;
    const float* Kg = Qg + SZ1;
    const float* Vg = Qg + 2 * SZ1;

    if (tid < 507) Bt[tid] = __ldg(&bias_table[tid * NHEAD + h]);

#pragma unroll
    for (int i = 0; i < 2; i++) {
        int idx = tid + i * 512;
        if (idx < 784) {
            int r = idx >> 3, c4 = idx & 7;
            float4 q = *(const float4*)(Qg + (size_t)idx * 4);
            float4 k = *(const float4*)(Kg + (size_t)idx * 4);
            float4 v = *(const float4*)(Vg + (size_t)idx * 4);
            int o = r * 36 + c4 * 4;
            *(float4*)&Qs[o] = f2tf4(q);
            *(float4*)&Ks[o] = f2tf4(k);
            *(float4*)&Vs[o] = f2tf4(v);
        }
    }
    if (tid < 504) Qs[98 * 36 + tid] = 0.f;
    if (tid < 216) { Ks[98 * 36 + tid] = 0.f; Vs[98 * 36 + tid] = 0.f; }
    __syncthreads();

    // ---- S = Q K^T ----
    for (int t = warp; t < 91; t += 16) {
        int mt = t / 13, nt = t - mt * 13;
        float c[4] = {0.f, 0.f, 0.f, 0.f};
        int ra = mt * 16 + (lane >> 2);
        int rb = nt * 8 + (lane >> 2);
#pragma unroll
        for (int ks = 0; ks < 4; ks++) {
            int kk = ks * 8 + (lane & 3);
            unsigned a0 = __float_as_uint(Qs[ra * 36 + kk]);
            unsigned a1 = __float_as_uint(Qs[(ra + 8) * 36 + kk]);
            unsigned a2 = __float_as_uint(Qs[ra * 36 + kk + 4]);
            unsigned a3 = __float_as_uint(Qs[(ra + 8) * 36 + kk + 4]);
            unsigned b0 = __float_as_uint(Ks[rb * 36 + kk]);
            unsigned b1 = __float_as_uint(Ks[rb * 36 + kk + 4]);
            mma8(c, a0, a1, a2, a3, b0, b1);
        }
        int row = mt * 16 + (lane >> 2);
        int col = nt * 8 + ((lane & 3) << 1);
        Ss[row * 108 + col]           = c[0];
        Ss[row * 108 + col + 1]       = c[1];
        Ss[(row + 8) * 108 + col]     = c[2];
        Ss[(row + 8) * 108 + col + 1] = c[3];
    }
    __syncthreads();

    // ---- bias + mask + softmax ----
    int coff[4];
#pragma unroll
    for (int j = 0; j < 4; j++) {
        int cidx = lane + j * 32;
        if (cidx < SEQ) {
            int zc = cidx / 49, rc = cidx - zc * 49;
            int yc = rc / 7, xc = rc - yc * 7;
            coff[j] = -(zc * 169 + yc * 13 + xc);
        } else coff[j] = 0;
    }
    const float* mbase = mask + (size_t)(b & 63) * SEQ * SEQ;
    for (int r = warp; r < SEQ; r += 16) {
        int zr = r / 49, rr = r - zr * 49;
        int yr = rr / 7, xr = rr - yr * 7;
        int base = (zr + 1) * 169 + (yr + 6) * 13 + (xr + 6);
        float* srow = Ss + r * 108;
        const float* mrow = mbase + r * SEQ;
        float v[4];
        float mx = -1e30f;
#pragma unroll
        for (int j = 0; j < 4; j++) {
            int cidx = lane + j * 32;
            if (cidx < SEQ) {
                v[j] = srow[cidx] + __ldg(&mrow[cidx]) + Bt[base + coff[j]];
                mx = fmaxf(mx, v[j]);
            } else {
                v[j] = -1e30f;
            }
        }
#pragma unroll
        for (int o = 16; o; o >>= 1) mx = fmaxf(mx, __shfl_xor_sync(0xffffffffu, mx, o));
        float s = 0.f;
#pragma unroll
        for (int j = 0; j < 4; j++) {
            float e = __expf(v[j] - mx);
            v[j] = e;
            s += e;
        }
#pragma unroll
        for (int o = 16; o; o >>= 1) s += __shfl_xor_sync(0xffffffffu, s, o);
        float inv = 1.f / s;
#pragma unroll
        for (int j = 0; j < 4; j++) {
            int cidx = lane + j * 32;
            if (cidx < SEQ) srow[cidx] = v[j] * inv;
        }
    }
    __syncthreads();

    // ---- O = P V ----
    float* Ob = g_O + (size_t)b * SEQ * 256 + h * 32;
    for (int t = warp; t < 28; t += 16) {
        int mt = t >> 2, nt = t & 3;
        float c[4] = {0.f, 0.f, 0.f, 0.f};
        int ra = mt * 16 + (lane >> 2);
        int cb = nt * 8 + (lane >> 2);
#pragma unroll
        for (int ks = 0; ks < 13; ks++) {
            int kk = ks * 8 + (lane & 3);
            unsigned a0 = f2tf(Ss[ra * 108 + kk]);
            unsigned a1 = f2tf(Ss[(ra + 8) * 108 + kk]);
            unsigned a2 = f2tf(Ss[ra * 108 + kk + 4]);
            unsigned a3 = f2tf(Ss[(ra + 8) * 108 + kk + 4]);
            unsigned b0 = __float_as_uint(Vs[kk * 36 + cb]);
            unsigned b1 = __float_as_uint(Vs[(kk + 4) * 36 + cb]);
            mma8(c, a0, a1, a2, a3, b0, b1);
        }
        int row = mt * 16 + (lane >> 2);
        int col = nt * 8 + ((lane & 3) << 1);
        if (row < SEQ)
            *(float2*)&Ob[(size_t)row * 256 + col] = make_float2(c[0], c[1]);
        if (row + 8 < SEQ)
            *(float2*)&Ob[(size_t)(row + 8) * 256 + col] = make_float2(c[2], c[3]);
    }
}

// ---------------------------------------------------------------------------
extern "C" void kernel_launch(void* const* d_in, const int* in_sizes, int n_in,
                              void* d_out, int out_size) {
    const float* x          = (const float*)d_in[0];
    const float* mask       = (const float*)d_in[1];
    const float* qkv_w      = (const float*)d_in[2];
    const float* proj_w     = (const float*)d_in[3];
    const float* proj_b     = (const float*)d_in[4];
    const float* bias_table = (const float*)d_in[5];
    float* out = (float*)d_out;

    (void)in_sizes; (void)n_in; (void)out_size;

    // QKV projection (fp16 mma): [200704,256] x [256,768] -> g_QKV
    gemm_f16<768, 0><<<dim3(6, 1568), 256>>>(x, qkv_w, nullptr, nullptr);

    // Fused attention (tf32, unchanged)
    cudaFuncSetAttribute(attn_kernel, cudaFuncAttributeMaxDynamicSharedMemorySize, 96496);
    attn_kernel<<<2048 * 8, 512, 96496>>>(mask, bias_table);

    // Output projection (fp16 mma): [200704,256] x [256,256] + bias -> d_out
    gemm_f16<256, 1><<<dim3(2, 1568), 256>>>(nullptr, proj_w, proj_b, out);
}

// round 15
// speedup vs baseline: 1.6659x; 1.2376x over previous
#include <cuda_runtime.h>
#include <cuda_fp16.h>
#include <cstdint>
#include <cstddef>

#define DEV __device__ __forceinline__

static constexpr int SEQ   = 98;
static constexpr int NHEAD = 8;
static constexpr float QK_SCALE = 0.17677669529663688f;  // 32^-0.5

// ---------------------------------------------------------------------------
// Scratch (static device globals — allocation-free per harness rules)
// ---------------------------------------------------------------------------
__device__ alignas(16) float g_QKV[(size_t)3 * 2048 * 8 * 98 * 32];
__device__ alignas(16) float g_O[(size_t)2048 * 98 * 256];

static constexpr size_t SZ1 = (size_t)2048 * 8 * 98 * 32;

DEV void mma16(float c[4], unsigned a0, unsigned a1, unsigned a2, unsigned a3,
               unsigned b0, unsigned b1) {
    asm volatile(
        "mma.sync.aligned.m16n8k16.row.col.f32.f16.f16.f32 "
        "{%0,%1,%2,%3}, {%4,%5,%6,%7}, {%8,%9}, {%0,%1,%2,%3};\n"
        : "+f"(c[0]), "+f"(c[1]), "+f"(c[2]), "+f"(c[3])
        : "r"(a0), "r"(a1), "r"(a2), "r"(a3), "r"(b0), "r"(b1));
}

DEV uint32_t smem_u32(const void* p) { return (uint32_t)__cvta_generic_to_shared(p); }

DEV void ldsm_x4(unsigned& r0, unsigned& r1, unsigned& r2, unsigned& r3, uint32_t a) {
    asm volatile("ldmatrix.sync.aligned.m8n8.x4.shared.b16 {%0,%1,%2,%3}, [%4];"
                 : "=r"(r0), "=r"(r1), "=r"(r2), "=r"(r3) : "r"(a));
}

DEV void ldsm_x2(unsigned& r0, unsigned& r1, uint32_t a) {
    asm volatile("ldmatrix.sync.aligned.m8n8.x2.shared.b16 {%0,%1}, [%2];"
                 : "=r"(r0), "=r"(r1) : "r"(a));
}

DEV void ldsm_x2t(unsigned& r0, unsigned& r1, uint32_t a) {
    asm volatile("ldmatrix.sync.aligned.m8n8.x2.trans.shared.b16 {%0,%1}, [%2];"
                 : "=r"(r0), "=r"(r1) : "r"(a));
}

DEV uint2 f4_to_h4(float4 v) {
    __half2 h0 = __floats2half2_rn(v.x, v.y);
    __half2 h1 = __floats2half2_rn(v.z, v.w);
    uint2 u;
    u.x = *reinterpret_cast<uint32_t*>(&h0);
    u.y = *reinterpret_cast<uint32_t*>(&h1);
    return u;
}

// ---------------------------------------------------------------------------
// FP16 K=256 GEMM, tile 128x128x32, 256 threads (2x4 warps, 64x32 each)
// Double-buffered smem: ONE bar per k-tile; LDG latency hidden under compute.
// ---------------------------------------------------------------------------
template <int NDIM, int EPI>
__global__ __launch_bounds__(256, 2) void gemm_f16(const float* __restrict__ A,
                                                   const float* __restrict__ B,
                                                   const float* __restrict__ bias,
                                                   float* __restrict__ Cout) {
    __shared__ __half As[2][128][40];
    __shared__ __half Bs[2][32][136];

    const int tid  = threadIdx.x;
    const int lane = tid & 31;
    const int warp = tid >> 5;
    const int wm = warp >> 2;
    const int wn = warp & 3;
    const int m0 = blockIdx.y * 128;
    const int n0 = blockIdx.x * 128;

    const float* Ap = (EPI == 1) ? (const float*)g_O : A;

    const int a_row = wm * 64 + (lane & 7) + ((lane >> 3) & 1) * 8;
    const uint32_t a_off = (uint32_t)(a_row * 80 + ((lane >> 4) & 1) * 16);
    const uint32_t b_off = (uint32_t)((lane & 15) * 136 + wn * 32) * 2;

    // per-thread load coordinates (same every tile)
    const int ra = tid >> 3, ca = (tid & 7) * 4;
    const int rb = tid >> 5, cb = (tid & 31) * 4;

    float acc[4][4][4];
#pragma unroll
    for (int i = 0; i < 4; i++)
#pragma unroll
        for (int j = 0; j < 4; j++)
#pragma unroll
            for (int e = 0; e < 4; e++) acc[i][j][e] = 0.f;

    // ---- prologue: tile 0 -> buf 0 ----
#pragma unroll
    for (int i = 0; i < 4; i++) {
        float4 v = *(const float4*)(Ap + (size_t)(m0 + ra + i * 32) * 256 + ca);
        *(uint2*)&As[0][ra + i * 32][ca] = f4_to_h4(v);
    }
#pragma unroll
    for (int i = 0; i < 4; i++) {
        float4 v = *(const float4*)(B + (size_t)(rb + i * 8) * NDIM + n0 + cb);
        *(uint2*)&Bs[0][rb + i * 8][cb] = f4_to_h4(v);
    }
    __syncthreads();

    for (int kt = 0; kt < 8; kt++) {
        const int cur = kt & 1;
        const int k1 = (kt + 1) * 32;

        // issue next tile's LDGs (latency overlaps compute below)
        float4 ar[4], br[4];
        if (k1 < 256) {
#pragma unroll
            for (int i = 0; i < 4; i++)
                ar[i] = *(const float4*)(Ap + (size_t)(m0 + ra + i * 32) * 256 + k1 + ca);
#pragma unroll
            for (int i = 0; i < 4; i++)
                br[i] = *(const float4*)(B + (size_t)(k1 + rb + i * 8) * NDIM + n0 + cb);
        }

        // compute current buffer
        const uint32_t a_base = smem_u32(&As[cur][0][0]) + a_off;
        const uint32_t b_base = smem_u32(&Bs[cur][0][0]) + b_off;
#pragma unroll
        for (int ks = 0; ks < 2; ks++) {
            unsigned af[4][4];
#pragma unroll
            for (int mt = 0; mt < 4; mt++)
                ldsm_x4(af[mt][0], af[mt][1], af[mt][2], af[mt][3],
                        a_base + (uint32_t)(mt * 16 * 80 + ks * 32));
            unsigned bf[4][2];
#pragma unroll
            for (int nt = 0; nt < 4; nt++)
                ldsm_x2t(bf[nt][0], bf[nt][1],
                         b_base + (uint32_t)(ks * 16 * 272 + nt * 16));
#pragma unroll
            for (int mt = 0; mt < 4; mt++)
#pragma unroll
                for (int nt = 0; nt < 4; nt++)
                    mma16(acc[mt][nt], af[mt][0], af[mt][1], af[mt][2], af[mt][3],
                          bf[nt][0], bf[nt][1]);
        }

        // store next tile (data has arrived during compute), then ONE bar
        if (k1 < 256) {
            const int nxt = cur ^ 1;
#pragma unroll
            for (int i = 0; i < 4; i++)
                *(uint2*)&As[nxt][ra + i * 32][ca] = f4_to_h4(ar[i]);
#pragma unroll
            for (int i = 0; i < 4; i++)
                *(uint2*)&Bs[nxt][rb + i * 8][cb] = f4_to_h4(br[i]);
            __syncthreads();
        }
    }

    // ---- epilogue (float2 stores) ----
#pragma unroll
    for (int mt = 0; mt < 4; mt++)
#pragma unroll
        for (int nt = 0; nt < 4; nt++)
#pragma unroll
            for (int half = 0; half < 2; half++) {
                int m = m0 + wm * 64 + mt * 16 + (lane >> 2) + half * 8;
                int c = n0 + wn * 32 + nt * 8 + ((lane & 3) << 1);
                float v0 = acc[mt][nt][half * 2 + 0];
                float v1 = acc[mt][nt][half * 2 + 1];
                if (EPI == 0) {
                    int bb = m / SEQ;
                    int n  = m - bb * SEQ;
                    int which = c >> 8;
                    int hh    = (c >> 5) & 7;
                    int d     = c & 31;
                    if (which == 0) { v0 *= QK_SCALE; v1 *= QK_SCALE; }
                    float* p = &g_QKV[(size_t)which * SZ1 +
                                      ((size_t)((bb * 8 + hh) * SEQ + n)) * 32 + d];
                    *(float2*)p = make_float2(v0, v1);
                } else {
                    float2 bv = *(const float2*)&bias[c];
                    *(float2*)&Cout[(size_t)m * 256 + c] =
                        make_float2(v0 + bv.x, v1 + bv.y);
                }
            }
}

// ---------------------------------------------------------------------------
// Fused window attention, FP16 mma + ldmatrix (FROZEN from R10/R11 audit).
// ---------------------------------------------------------------------------
__global__ __launch_bounds__(512, 2) void attn_f16(const float* __restrict__ mask,
                                                   const float* __restrict__ bias_table) {
    extern __shared__ char smraw[];
    __half* Qh = (__half*)smraw;          // 112*40 = 4480 halves
    __half* Kh = Qh + 4480;               // 104*40 = 4160
    __half* Vh = Kh + 4160;               // 112*40 = 4480
    float*  Sf = (float*)(Vh + 4480);     // 112*108 floats
    float*  Bt = Sf + 112 * 108;          // 507

    const int tid  = threadIdx.x;
    const int lane = tid & 31;
    const int warp = tid >> 5;   // 0..15
    const int b = blockIdx.x >> 3;
    const int h = blockIdx.x & 7;

    const float* Qg = g_QKV + (size_t)(b * 8 + h) * SEQ * 32;
    const float* Kg = Qg + SZ1;
    const float* Vg = Qg + 2 * SZ1;

    if (tid < 507) Bt[tid] = __ldg(&bias_table[tid * NHEAD + h]);

#pragma unroll
    for (int i = 0; i < 2; i++) {
        int idx = tid + i * 512;
        if (idx < 784) {
            int r = idx >> 3, c4 = idx & 7;
            float4 q = *(const float4*)(Qg + (size_t)idx * 4);
            float4 k = *(const float4*)(Kg + (size_t)idx * 4);
            float4 v = *(const float4*)(Vg + (size_t)idx * 4);
            int o = r * 40 + c4 * 4;
            *(uint2*)&Qh[o] = f4_to_h4(q);
            *(uint2*)&Kh[o] = f4_to_h4(k);
            *(uint2*)&Vh[o] = f4_to_h4(v);
        }
    }
    if (tid < 280) ((uint32_t*)(Qh + 98 * 40))[tid] = 0u;
    if (tid < 120) ((uint32_t*)(Kh + 98 * 40))[tid] = 0u;
    if (tid < 280) ((uint32_t*)(Vh + 98 * 40))[tid] = 0u;
    __syncthreads();

    // ---- S = Q K^T ----
    {
        const uint32_t qa = smem_u32(Qh) + (uint32_t)((lane & 15) * 80 + (lane >> 4) * 16);
        const uint32_t kb = smem_u32(Kh) + (uint32_t)((lane & 7) * 80 + ((lane >> 3) & 1) * 16);
        for (int t = warp; t < 91; t += 16) {
            int mt = t / 13, nt = t - mt * 13;
            float c[4] = {0.f, 0.f, 0.f, 0.f};
#pragma unroll
            for (int ks = 0; ks < 2; ks++) {
                unsigned a0, a1, a2, a3, b0, b1;
                ldsm_x4(a0, a1, a2, a3, qa + (uint32_t)(mt * 16 * 80 + ks * 32));
                ldsm_x2(b0, b1, kb + (uint32_t)(nt * 8 * 80 + ks * 32));
                mma16(c, a0, a1, a2, a3, b0, b1);
            }
            int row = mt * 16 + (lane >> 2);
            int col = nt * 8 + ((lane & 3) << 1);
            *(float2*)&Sf[row * 108 + col]       = make_float2(c[0], c[1]);
            *(float2*)&Sf[(row + 8) * 108 + col] = make_float2(c[2], c[3]);
        }
    }
    __syncthreads();

    // ---- bias + mask + softmax; write P (half) aliased over Sf rows ----
    int coff[4];
#pragma unroll
    for (int j = 0; j < 4; j++) {
        int cidx = lane + j * 32;
        if (cidx < SEQ) {
            int zc = cidx / 49, rc = cidx - zc * 49;
            int yc = rc / 7, xc = rc - yc * 7;
            coff[j] = -(zc * 169 + yc * 13 + xc);
        } else coff[j] = 0;
    }
    const float* mbase = mask + (size_t)(b & 63) * SEQ * SEQ;
    for (int r = warp; r < SEQ; r += 16) {
        int zr = r / 49, rr = r - zr * 49;
        int yr = rr / 7, xr = rr - yr * 7;
        int base = (zr + 1) * 169 + (yr + 6) * 13 + (xr + 6);
        float* srow = Sf + r * 108;
        const float* mrow = mbase + r * SEQ;
        float v[4];
        float mx = -1e30f;
#pragma unroll
        for (int j = 0; j < 4; j++) {
            int cidx = lane + j * 32;
            if (cidx < SEQ) {
                v[j] = srow[cidx] + __ldg(&mrow[cidx]) + Bt[base + coff[j]];
                mx = fmaxf(mx, v[j]);
            } else {
                v[j] = -1e30f;
            }
        }
#pragma unroll
        for (int o = 16; o; o >>= 1) mx = fmaxf(mx, __shfl_xor_sync(0xffffffffu, mx, o));
        float s = 0.f;
#pragma unroll
        for (int j = 0; j < 4; j++) {
            float e = __expf(v[j] - mx);
            v[j] = e;
            s += e;
        }
#pragma unroll
        for (int o = 16; o; o >>= 1) s += __shfl_xor_sync(0xffffffffu, s, o);
        float inv = 1.f / s;
        __half* prow = (__half*)((char*)Sf + (size_t)r * 432);
#pragma unroll
        for (int j = 0; j < 4; j++) {
            int cidx = lane + j * 32;
            if (cidx < SEQ)       prow[cidx] = __float2half_rn(v[j] * inv);
            else if (cidx < 112)  prow[cidx] = __ushort_as_half(0);
        }
    }
    __syncthreads();

    // ---- O = P V ----
    {
        const uint32_t pa = smem_u32(Sf) + (uint32_t)((lane & 15) * 432 + (lane >> 4) * 16);
        const uint32_t vb = smem_u32(Vh) + (uint32_t)((lane & 15) * 80);
        float* Ob = g_O + (size_t)b * SEQ * 256 + h * 32;
        for (int t = warp; t < 28; t += 16) {
            int mt = t >> 2, nt = t & 3;
            float c[4] = {0.f, 0.f, 0.f, 0.f};
#pragma unroll
            for (int ks = 0; ks < 7; ks++) {
                unsigned a0, a1, a2, a3, b0, b1;
                ldsm_x4(a0, a1, a2, a3, pa + (uint32_t)(mt * 16 * 432 + ks * 32));
                ldsm_x2t(b0, b1, vb + (uint32_t)(ks * 16 * 80 + nt * 16));
                mma16(c, a0, a1, a2, a3, b0, b1);
            }
            int row = mt * 16 + (lane >> 2);
            int col = nt * 8 + ((lane & 3) << 1);
            if (row < SEQ)
                *(float2*)&Ob[(size_t)row * 256 + col] = make_float2(c[0], c[1]);
            if (row + 8 < SEQ)
                *(float2*)&Ob[(size_t)(row + 8) * 256 + col] = make_float2(c[2], c[3]);
        }
    }
}

// ---------------------------------------------------------------------------
extern "C" void kernel_launch(void* const* d_in, const int* in_sizes, int n_in,
                              void* d_out, int out_size) {
    const float* x          = (const float*)d_in[0];
    const float* mask       = (const float*)d_in[1];
    const float* qkv_w      = (const float*)d_in[2];
    const float* proj_w     = (const float*)d_in[3];
    const float* proj_b     = (const float*)d_in[4];
    const float* bias_table = (const float*)d_in[5];
    float* out = (float*)d_out;

    (void)in_sizes; (void)n_in; (void)out_size;

    // QKV projection (fp16 mma, double-buffered): [200704,256]x[256,768]
    gemm_f16<768, 0><<<dim3(6, 1568), 256>>>(x, qkv_w, nullptr, nullptr);

    // Fused attention (fp16 mma + ldmatrix)
    cudaFuncSetAttribute(attn_f16, cudaFuncAttributeMaxDynamicSharedMemorySize, 76656);
    attn_f16<<<2048 * 8, 512, 76656>>>(mask, bias_table);

    // Output projection (fp16 mma, double-buffered): [200704,256]x[256,256]+bias
    gemm_f16<256, 1><<<dim3(2, 1568), 256>>>(nullptr, proj_w, proj_b, out);
}

// round 16
// speedup vs baseline: 1.7761x; 1.0662x over previous
#include <cuda_runtime.h>
#include <cuda_fp16.h>
#include <cstdint>
#include <cstddef>

#define DEV __device__ __forceinline__

static constexpr int SEQ   = 98;
static constexpr int NHEAD = 8;
static constexpr float QK_SCALE = 0.17677669529663688f;  // 32^-0.5

// ---------------------------------------------------------------------------
// Scratch (static device globals — allocation-free per harness rules)
// ---------------------------------------------------------------------------
__device__ alignas(16) float g_QKV[(size_t)3 * 2048 * 8 * 98 * 32];
__device__ alignas(16) float g_O[(size_t)2048 * 98 * 256];

static constexpr size_t SZ1 = (size_t)2048 * 8 * 98 * 32;

DEV void mma16(float c[4], unsigned a0, unsigned a1, unsigned a2, unsigned a3,
               unsigned b0, unsigned b1) {
    asm volatile(
        "mma.sync.aligned.m16n8k16.row.col.f32.f16.f16.f32 "
        "{%0,%1,%2,%3}, {%4,%5,%6,%7}, {%8,%9}, {%0,%1,%2,%3};\n"
        : "+f"(c[0]), "+f"(c[1]), "+f"(c[2]), "+f"(c[3])
        : "r"(a0), "r"(a1), "r"(a2), "r"(a3), "r"(b0), "r"(b1));
}

DEV uint32_t smem_u32(const void* p) { return (uint32_t)__cvta_generic_to_shared(p); }

DEV void ldsm_x4(unsigned& r0, unsigned& r1, unsigned& r2, unsigned& r3, uint32_t a) {
    asm volatile("ldmatrix.sync.aligned.m8n8.x4.shared.b16 {%0,%1,%2,%3}, [%4];"
                 : "=r"(r0), "=r"(r1), "=r"(r2), "=r"(r3) : "r"(a));
}

DEV void ldsm_x2(unsigned& r0, unsigned& r1, uint32_t a) {
    asm volatile("ldmatrix.sync.aligned.m8n8.x2.shared.b16 {%0,%1}, [%2];"
                 : "=r"(r0), "=r"(r1) : "r"(a));
}

DEV void ldsm_x2t(unsigned& r0, unsigned& r1, uint32_t a) {
    asm volatile("ldmatrix.sync.aligned.m8n8.x2.trans.shared.b16 {%0,%1}, [%2];"
                 : "=r"(r0), "=r"(r1) : "r"(a));
}

DEV uint2 f4_to_h4(float4 v) {
    __half2 h0 = __floats2half2_rn(v.x, v.y);
    __half2 h1 = __floats2half2_rn(v.z, v.w);
    uint2 u;
    u.x = *reinterpret_cast<uint32_t*>(&h0);
    u.y = *reinterpret_cast<uint32_t*>(&h1);
    return u;
}

// ---------------------------------------------------------------------------
// FP16 K=256 GEMM, tile 128x128x32, 256 threads — FROZEN (measured R15)
// ---------------------------------------------------------------------------
template <int NDIM, int EPI>
__global__ __launch_bounds__(256, 2) void gemm_f16(const float* __restrict__ A,
                                                   const float* __restrict__ B,
                                                   const float* __restrict__ bias,
                                                   float* __restrict__ Cout) {
    __shared__ __half As[2][128][40];
    __shared__ __half Bs[2][32][136];

    const int tid  = threadIdx.x;
    const int lane = tid & 31;
    const int warp = tid >> 5;
    const int wm = warp >> 2;
    const int wn = warp & 3;
    const int m0 = blockIdx.y * 128;
    const int n0 = blockIdx.x * 128;

    const float* Ap = (EPI == 1) ? (const float*)g_O : A;

    const int a_row = wm * 64 + (lane & 7) + ((lane >> 3) & 1) * 8;
    const uint32_t a_off = (uint32_t)(a_row * 80 + ((lane >> 4) & 1) * 16);
    const uint32_t b_off = (uint32_t)((lane & 15) * 136 + wn * 32) * 2;

    const int ra = tid >> 3, ca = (tid & 7) * 4;
    const int rb = tid >> 5, cb = (tid & 31) * 4;

    float acc[4][4][4];
#pragma unroll
    for (int i = 0; i < 4; i++)
#pragma unroll
        for (int j = 0; j < 4; j++)
#pragma unroll
            for (int e = 0; e < 4; e++) acc[i][j][e] = 0.f;

#pragma unroll
    for (int i = 0; i < 4; i++) {
        float4 v = *(const float4*)(Ap + (size_t)(m0 + ra + i * 32) * 256 + ca);
        *(uint2*)&As[0][ra + i * 32][ca] = f4_to_h4(v);
    }
#pragma unroll
    for (int i = 0; i < 4; i++) {
        float4 v = *(const float4*)(B + (size_t)(rb + i * 8) * NDIM + n0 + cb);
        *(uint2*)&Bs[0][rb + i * 8][cb] = f4_to_h4(v);
    }
    __syncthreads();

    for (int kt = 0; kt < 8; kt++) {
        const int cur = kt & 1;
        const int k1 = (kt + 1) * 32;

        float4 ar[4], br[4];
        if (k1 < 256) {
#pragma unroll
            for (int i = 0; i < 4; i++)
                ar[i] = *(const float4*)(Ap + (size_t)(m0 + ra + i * 32) * 256 + k1 + ca);
#pragma unroll
            for (int i = 0; i < 4; i++)
                br[i] = *(const float4*)(B + (size_t)(k1 + rb + i * 8) * NDIM + n0 + cb);
        }

        const uint32_t a_base = smem_u32(&As[cur][0][0]) + a_off;
        const uint32_t b_base = smem_u32(&Bs[cur][0][0]) + b_off;
#pragma unroll
        for (int ks = 0; ks < 2; ks++) {
            unsigned af[4][4];
#pragma unroll
            for (int mt = 0; mt < 4; mt++)
                ldsm_x4(af[mt][0], af[mt][1], af[mt][2], af[mt][3],
                        a_base + (uint32_t)(mt * 16 * 80 + ks * 32));
            unsigned bf[4][2];
#pragma unroll
            for (int nt = 0; nt < 4; nt++)
                ldsm_x2t(bf[nt][0], bf[nt][1],
                         b_base + (uint32_t)(ks * 16 * 272 + nt * 16));
#pragma unroll
            for (int mt = 0; mt < 4; mt++)
#pragma unroll
                for (int nt = 0; nt < 4; nt++)
                    mma16(acc[mt][nt], af[mt][0], af[mt][1], af[mt][2], af[mt][3],
                          bf[nt][0], bf[nt][1]);
        }

        if (k1 < 256) {
            const int nxt = cur ^ 1;
#pragma unroll
            for (int i = 0; i < 4; i++)
                *(uint2*)&As[nxt][ra + i * 32][ca] = f4_to_h4(ar[i]);
#pragma unroll
            for (int i = 0; i < 4; i++)
                *(uint2*)&Bs[nxt][rb + i * 8][cb] = f4_to_h4(br[i]);
            __syncthreads();
        }
    }

#pragma unroll
    for (int mt = 0; mt < 4; mt++)
#pragma unroll
        for (int nt = 0; nt < 4; nt++)
#pragma unroll
            for (int half = 0; half < 2; half++) {
                int m = m0 + wm * 64 + mt * 16 + (lane >> 2) + half * 8;
                int c = n0 + wn * 32 + nt * 8 + ((lane & 3) << 1);
                float v0 = acc[mt][nt][half * 2 + 0];
                float v1 = acc[mt][nt][half * 2 + 1];
                if (EPI == 0) {
                    int bb = m / SEQ;
                    int n  = m - bb * SEQ;
                    int which = c >> 8;
                    int hh    = (c >> 5) & 7;
                    int d     = c & 31;
                    if (which == 0) { v0 *= QK_SCALE; v1 *= QK_SCALE; }
                    float* p = &g_QKV[(size_t)which * SZ1 +
                                      ((size_t)((bb * 8 + hh) * SEQ + n)) * 32 + d];
                    *(float2*)p = make_float2(v0, v1);
                } else {
                    float2 bv = *(const float2*)&bias[c];
                    *(float2*)&Cout[(size_t)m * 256 + c] =
                        make_float2(v0 + bv.x, v1 + bv.y);
                }
            }
}

// ---------------------------------------------------------------------------
// Fused window attention v2: fp16 S buffer -> 55.1KB smem -> 3 CTAs/SM.
// Smem halves: Qh[112][40] Kh[104][40] Vh[112][40] Sh[112][120]; Bt float[507]
// Layout (half idx): Qh@0  Kh@4480  Vh@8640  Sh@13120  | Bt @byte 53120
// ---------------------------------------------------------------------------
__global__ __launch_bounds__(512, 3) void attn_f16(const float* __restrict__ mask,
                                                   const float* __restrict__ bias_table) {
    extern __shared__ char smraw[];
    __half* Qh = (__half*)smraw;
    __half* Kh = Qh + 4480;
    __half* Vh = Kh + 4160;
    __half* Sh = Vh + 4480;               // [112][120] halves, 240B row stride
    float*  Bt = (float*)(Sh + 13440);    // 507 floats

    const int tid  = threadIdx.x;
    const int lane = tid & 31;
    const int warp = tid >> 5;   // 0..15
    const int b = blockIdx.x >> 3;
    const int h = blockIdx.x & 7;

    const float* Qg = g_QKV + (size_t)(b * 8 + h) * SEQ * 32;
    const float* Kg = Qg + SZ1;
    const float* Vg = Qg + 2 * SZ1;

    if (tid < 507) Bt[tid] = __ldg(&bias_table[tid * NHEAD + h]);

#pragma unroll
    for (int i = 0; i < 2; i++) {
        int idx = tid + i * 512;
        if (idx < 784) {
            int r = idx >> 3, c4 = idx & 7;
            float4 q = *(const float4*)(Qg + (size_t)idx * 4);
            float4 k = *(const float4*)(Kg + (size_t)idx * 4);
            float4 v = *(const float4*)(Vg + (size_t)idx * 4);
            int o = r * 40 + c4 * 4;
            *(uint2*)&Qh[o] = f4_to_h4(q);
            *(uint2*)&Kh[o] = f4_to_h4(k);
            *(uint2*)&Vh[o] = f4_to_h4(v);
        }
    }
    // zero pads: Qh rows 98..111, Kh rows 98..103, Vh rows 98..111
    if (tid < 280) ((uint32_t*)(Qh + 98 * 40))[tid] = 0u;
    if (tid < 120) ((uint32_t*)(Kh + 98 * 40))[tid] = 0u;
    if (tid < 280) ((uint32_t*)(Vh + 98 * 40))[tid] = 0u;
    // zero Sh pad rows 98..111 (cols 104..119 never written by QK; rest overwritten w/ 0)
    for (int i = tid; i < 840; i += 512) ((uint32_t*)(Sh + 98 * 120))[i] = 0u;
    __syncthreads();

    // ---- S = Q K^T : 7 (m16) x 13 (n8) tiles, 2 k16-steps; store fp16 ----
    {
        const uint32_t qa = smem_u32(Qh) + (uint32_t)((lane & 15) * 80 + (lane >> 4) * 16);
        const uint32_t kb = smem_u32(Kh) + (uint32_t)((lane & 7) * 80 + ((lane >> 3) & 1) * 16);
        for (int t = warp; t < 91; t += 16) {
            int mt = t / 13, nt = t - mt * 13;
            float c[4] = {0.f, 0.f, 0.f, 0.f};
#pragma unroll
            for (int ks = 0; ks < 2; ks++) {
                unsigned a0, a1, a2, a3, b0, b1;
                ldsm_x4(a0, a1, a2, a3, qa + (uint32_t)(mt * 16 * 80 + ks * 32));
                ldsm_x2(b0, b1, kb + (uint32_t)(nt * 8 * 80 + ks * 32));
                mma16(c, a0, a1, a2, a3, b0, b1);
            }
            int row = mt * 16 + (lane >> 2);
            int col = nt * 8 + ((lane & 3) << 1);
            __half2 lo = __floats2half2_rn(c[0], c[1]);
            __half2 hi = __floats2half2_rn(c[2], c[3]);
            *(__half2*)&Sh[row * 120 + col]       = lo;
            *(__half2*)&Sh[(row + 8) * 120 + col] = hi;
        }
    }
    __syncthreads();

    // ---- bias + mask + softmax over fp16 S (math in fp32), in-place ----
    int coff[4];
#pragma unroll
    for (int j = 0; j < 4; j++) {
        int cidx = lane + j * 32;
        if (cidx < SEQ) {
            int zc = cidx / 49, rc = cidx - zc * 49;
            int yc = rc / 7, xc = rc - yc * 7;
            coff[j] = -(zc * 169 + yc * 13 + xc);
        } else coff[j] = 0;
    }
    const float* mbase = mask + (size_t)(b & 63) * SEQ * SEQ;
    for (int r = warp; r < SEQ; r += 16) {
        int zr = r / 49, rr = r - zr * 49;
        int yr = rr / 7, xr = rr - yr * 7;
        int base = (zr + 1) * 169 + (yr + 6) * 13 + (xr + 6);
        __half* srow = Sh + r * 120;
        const float* mrow = mbase + r * SEQ;
        float v[4];
        float mx = -1e30f;
#pragma unroll
        for (int j = 0; j < 4; j++) {
            int cidx = lane + j * 32;
            if (cidx < SEQ) {
                v[j] = __half2float(srow[cidx]) + __ldg(&mrow[cidx]) + Bt[base + coff[j]];
                mx = fmaxf(mx, v[j]);
            } else {
                v[j] = -1e30f;
            }
        }
#pragma unroll
        for (int o = 16; o; o >>= 1) mx = fmaxf(mx, __shfl_xor_sync(0xffffffffu, mx, o));
        float s = 0.f;
#pragma unroll
        for (int j = 0; j < 4; j++) {
            float e = __expf(v[j] - mx);
            v[j] = e;
            s += e;
        }
#pragma unroll
        for (int o = 16; o; o >>= 1) s += __shfl_xor_sync(0xffffffffu, s, o);
        float inv = 1.f / s;
#pragma unroll
        for (int j = 0; j < 4; j++) {
            int cidx = lane + j * 32;
            if (cidx < SEQ)       srow[cidx] = __float2half_rn(v[j] * inv);
            else if (cidx < 112)  srow[cidx] = __ushort_as_half(0);  // pad k cols
        }
    }
    __syncthreads();

    // ---- O = P V : 7 (m16) x 4 (n8) tiles, 7 k16-steps ----
    {
        const uint32_t pa = smem_u32(Sh) + (uint32_t)((lane & 15) * 240 + (lane >> 4) * 16);
        const uint32_t vb = smem_u32(Vh) + (uint32_t)((lane & 15) * 80);
        float* Ob = g_O + (size_t)b * SEQ * 256 + h * 32;
        for (int t = warp; t < 28; t += 16) {
            int mt = t >> 2, nt = t & 3;
            float c[4] = {0.f, 0.f, 0.f, 0.f};
#pragma unroll
            for (int ks = 0; ks < 7; ks++) {
                unsigned a0, a1, a2, a3, b0, b1;
                ldsm_x4(a0, a1, a2, a3, pa + (uint32_t)(mt * 16 * 240 + ks * 32));
                ldsm_x2t(b0, b1, vb + (uint32_t)(ks * 16 * 80 + nt * 16));
                mma16(c, a0, a1, a2, a3, b0, b1);
            }
            int row = mt * 16 + (lane >> 2);
            int col = nt * 8 + ((lane & 3) << 1);
            if (row < SEQ)
                *(float2*)&Ob[(size_t)row * 256 + col] = make_float2(c[0], c[1]);
            if (row + 8 < SEQ)
                *(float2*)&Ob[(size_t)(row + 8) * 256 + col] = make_float2(c[2], c[3]);
        }
    }
}

// ---------------------------------------------------------------------------
extern "C" void kernel_launch(void* const* d_in, const int* in_sizes, int n_in,
                              void* d_out, int out_size) {
    const float* x          = (const float*)d_in[0];
    const float* mask       = (const float*)d_in[1];
    const float* qkv_w      = (const float*)d_in[2];
    const float* proj_w     = (const float*)d_in[3];
    const float* proj_b     = (const float*)d_in[4];
    const float* bias_table = (const float*)d_in[5];
    float* out = (float*)d_out;

    (void)in_sizes; (void)n_in; (void)out_size;

    // QKV projection (fp16 mma, double-buffered): [200704,256]x[256,768]
    gemm_f16<768, 0><<<dim3(6, 1568), 256>>>(x, qkv_w, nullptr, nullptr);

    // Fused attention (fp16 S buffer, 3 CTAs/SM)
    cudaFuncSetAttribute(attn_f16, cudaFuncAttributeMaxDynamicSharedMemorySize, 55152);
    attn_f16<<<2048 * 8, 512, 55152>>>(mask, bias_table);

    // Output projection (fp16 mma, double-buffered): [200704,256]x[256,256]+bias
    gemm_f16<256, 1><<<dim3(2, 1568), 256>>>(nullptr, proj_w, proj_b, out);
}